// round 17
// baseline (speedup 1.0000x reference)
#include <cuda_runtime.h>
#include <cstdint>

// Problem constants (fixed by the reference)
#define HDIM 128
#define WDIM 128
#define DDIM 8
#define CDIM 64
#define NROI 80          // B(16) * 5 keypoints
#define CS   16.0f       // crop half-size = H * 1/8
#define FP   36          // max footprint (rows/cols) per ROI: 2*CS + slack
#define NC   4           // channels per block

__global__ __launch_bounds__(256, 8)
void roi_align_25d_kernel(const float* __restrict__ fea,
                          const float* __restrict__ kp,
                          float* __restrict__ out)
{
    const int c0  = blockIdx.x * NC;     // first channel of this block
    const int roi = blockIdx.y;          // 0..79
    const int b   = roi / 5;
    const int tid = threadIdx.x;

    __shared__ float Wy[2][FP];
    __shared__ float Wx[2][FP];
    __shared__ float tmp[NC][2][FP * DDIM];  // (ch, ph, xi*8+d)

    // ---- per-ROI scalar params (computed redundantly; cheap) ----
    const float kx   = kp[roi * 3 + 0] * (float)WDIM;
    const float ky   = kp[roi * 3 + 1] * (float)HDIM;
    const float xmin = fminf(fmaxf(kx - CS, 0.0f), (float)WDIM - 1.0f);
    const float xmax = fminf(fmaxf(kx + CS, 0.0f), (float)WDIM - 1.0f);
    const float ymin = fminf(fmaxf(ky - CS, 0.0f), (float)HDIM - 1.0f);
    const float ymax = fminf(fmaxf(ky + CS, 0.0f), (float)HDIM - 1.0f);
    const float roi_w = fmaxf(xmax - xmin, 1.0f);
    const float roi_h = fmaxf(ymax - ymin, 1.0f);
    const float bin_w = roi_w * 0.5f;    // PW = 2
    const float bin_h = roi_h * 0.5f;    // PH = 2
    const int   gw    = (int)ceilf(roi_w * 0.5f);   // 1..16
    const int   gh    = (int)ceilf(roi_h * 0.5f);   // 1..16
    const int   base_y = (int)floorf(ymin);
    const int   base_x = (int)floorf(xmin);
    // sample coords are strictly < min + roi_{h,w}; indices used are
    // [base, min(size-1, floor(min+roi)+1)]
    const int   cnt_y = min(HDIM - 1, (int)floorf(ymin + roi_h) + 1) - base_y + 1;
    const int   cnt_x = min(WDIM - 1, (int)floorf(xmin + roi_w) + 1) - base_x + 1;
    const float inv_count = 1.0f / (float)(gh * gw);

    // ---- zero weight arrays ----
    if (tid < 2 * FP) {
        (&Wy[0][0])[tid] = 0.0f;
        (&Wx[0][0])[tid] = 0.0f;
    }
    __syncthreads();

    // ---- build separable per-axis weights (thread = (axis, ph, g) sample) ----
    if (tid < 64) {
        const bool isx  = (tid >= 32);
        const int  ph   = (tid & 31) >> 4;     // 0..1
        const int  g    = tid & 15;            // 0..15
        const int  gcnt = isx ? gw : gh;
        if (g < gcnt) {
            const float mn   = isx ? xmin  : ymin;
            const float bn   = isx ? bin_w : bin_h;
            const int   size = isx ? WDIM  : HDIM;
            const int   base = isx ? base_x : base_y;
            // coord >= mn >= 0 always (mn clipped into [0, size-1])
            const float coord = mn + (float)ph * bn
                              + ((float)g + 0.5f) * (bn / (float)gcnt);
            const int l0 = (int)floorf(coord);
            int lo, hi; float frac;
            if (l0 >= size - 1) { lo = size - 1; hi = size - 1; frac = 0.0f; }
            else                { lo = l0;       hi = l0 + 1;   frac = coord - (float)l0; }
            float* Wp = isx ? &Wx[ph][0] : &Wy[ph][0];
            atomicAdd(&Wp[lo - base], 1.0f - frac);
            atomicAdd(&Wp[hi - base], frac);
        }
    }
    __syncthreads();

    // ---- pass 1: reduce over y for NC channels with float4 loads ----
    // unit = (ch, quad); quad indexes a float4 within the row (DDIM=8 -> 2/x).
    const int nquads = cnt_x * (DDIM / 4);           // <= 68
    const int nunits = nquads * NC;                  // <= 272
    const float* fbase = fea +
        ((((size_t)(b * CDIM + c0)) * HDIM + base_y) * WDIM + base_x) * DDIM;

    for (int u = tid; u < nunits; u += 256) {
        const int ch = u / nquads;
        const int q  = u - ch * nquads;
        const float4* p = (const float4*)(fbase + (size_t)ch * (HDIM * WDIM * DDIM)) + q;
        float4 a0 = make_float4(0.f, 0.f, 0.f, 0.f);
        float4 a1 = make_float4(0.f, 0.f, 0.f, 0.f);
        #pragma unroll 8
        for (int yi = 0; yi < cnt_y; yi++) {
            const float4 v  = p[(size_t)yi * (WDIM * DDIM / 4)];
            const float  w0 = Wy[0][yi];
            const float  w1 = Wy[1][yi];
            a0.x += w0 * v.x;  a0.y += w0 * v.y;  a0.z += w0 * v.z;  a0.w += w0 * v.w;
            a1.x += w1 * v.x;  a1.y += w1 * v.y;  a1.z += w1 * v.z;  a1.w += w1 * v.w;
        }
        ((float4*)&tmp[ch][0][0])[q] = a0;
        ((float4*)&tmp[ch][1][0])[q] = a1;
    }
    __syncthreads();

    // ---- pass 2: reduce over x for all NC channels in parallel ----
    if (tid < 32 * NC) {
        const int ch   = tid >> 5;
        const int lane = tid & 31;
        const int di = lane & 7;
        const int pw = (lane >> 3) & 1;
        const int ph = lane >> 4;
        float acc = 0.0f;
        for (int xi = 0; xi < cnt_x; xi++)
            acc += Wx[pw][xi] * tmp[ch][ph][xi * DDIM + di];
        acc *= inv_count;
        // out layout: (b, 5, c, PH, PW, D)
        out[((size_t)roi * CDIM + c0 + ch) * 32 + ph * 16 + pw * 8 + di] = acc;
    }
}

extern "C" void kernel_launch(void* const* d_in, const int* in_sizes, int n_in,
                              void* d_out, int out_size)
{
    // Defensive input-order resolution: fea has 8,388,608 elements; kp has 240.
    int fi = 0, ki = 1;
    if (n_in >= 2 && in_sizes[0] < in_sizes[1]) { fi = 1; ki = 0; }
    const float* fea = (const float*)d_in[fi];
    const float* kp  = (const float*)d_in[ki];
    float* out       = (float*)d_out;           // (16,5,64,2,2,8) fp32

    dim3 grid(CDIM / NC, NROI);   // (16, 80) = 1280 blocks
    roi_align_25d_kernel<<<grid, 256>>>(fea, kp, out);
}